// round 1
// baseline (speedup 1.0000x reference)
#include <cuda_runtime.h>
#include <math.h>

// Problem constants
// N=4, L=2048, E=512, H=8, D=64, FF=2048, tokens M = 8192
#define MTOK 8192
#define EDIM 512
#define FFDIM 2048

// -------- scratch (device globals: allocation-guard safe) --------
__device__ float g_h  [MTOK * EDIM];         // LN1 output
__device__ float g_q  [MTOK * EDIM];
__device__ float g_k  [MTOK * EDIM];
__device__ float g_v  [MTOK * EDIM];
__device__ float g_att[MTOK * EDIM];         // attention output pre O-proj
__device__ float g_x1 [MTOK * EDIM];         // after O-proj + residual
__device__ float g_h2 [MTOK * EDIM];         // LN2 output
__device__ float g_f1 [MTOK * FFDIM];        // silu(ffn1)
__device__ float g_sc [134217728];           // scores: 4*8*2048*2048

// -------- reductions --------
static __device__ __forceinline__ float warpReduceSum(float v) {
    #pragma unroll
    for (int o = 16; o > 0; o >>= 1) v += __shfl_xor_sync(0xffffffffu, v, o);
    return v;
}
static __device__ __forceinline__ float warpReduceMax(float v) {
    #pragma unroll
    for (int o = 16; o > 0; o >>= 1) v = fmaxf(v, __shfl_xor_sync(0xffffffffu, v, o));
    return v;
}

// -------- LayerNorm: one block per row of 512 --------
__global__ __launch_bounds__(128)
void layernorm_kernel(const float* __restrict__ x, const float* __restrict__ g,
                      const float* __restrict__ b, float* __restrict__ out)
{
    long row = blockIdx.x;
    int tid = threadIdx.x;
    const float4 v = ((const float4*)(x + row * EDIM))[tid];
    float s  = v.x + v.y + v.z + v.w;
    float ss = v.x*v.x + v.y*v.y + v.z*v.z + v.w*v.w;
    s  = warpReduceSum(s);
    ss = warpReduceSum(ss);
    __shared__ float sA[4], sB[4];
    if ((tid & 31) == 0) { sA[tid >> 5] = s; sB[tid >> 5] = ss; }
    __syncthreads();
    float ts  = sA[0] + sA[1] + sA[2] + sA[3];
    float tss = sB[0] + sB[1] + sB[2] + sB[3];
    float mean = ts * (1.0f / 512.0f);
    float var  = tss * (1.0f / 512.0f) - mean * mean;
    float r = rsqrtf(var + 1e-5f);
    const float4 gv = ((const float4*)g)[tid];
    const float4 bv = ((const float4*)b)[tid];
    float4 o;
    o.x = (v.x - mean) * r * gv.x + bv.x;
    o.y = (v.y - mean) * r * gv.y + bv.y;
    o.z = (v.z - mean) * r * gv.z + bv.z;
    o.w = (v.w - mean) * r * gv.w + bv.w;
    ((float4*)(out + row * EDIM))[tid] = o;
}

// -------- row softmax over 2048 columns --------
__global__ __launch_bounds__(256)
void softmax_kernel(float* __restrict__ S)
{
    float* p = S + (long)blockIdx.x * 2048;
    int tid = threadIdx.x;
    float v[8];
    float m = -1e30f;
    #pragma unroll
    for (int i = 0; i < 8; i++) { v[i] = p[tid + i * 256]; m = fmaxf(m, v[i]); }
    m = warpReduceMax(m);
    __shared__ float sM[8], sS[8];
    if ((tid & 31) == 0) sM[tid >> 5] = m;
    __syncthreads();
    float M = sM[0];
    #pragma unroll
    for (int i = 1; i < 8; i++) M = fmaxf(M, sM[i]);
    float s = 0.f;
    #pragma unroll
    for (int i = 0; i < 8; i++) { v[i] = __expf(v[i] - M); s += v[i]; }
    s = warpReduceSum(s);
    if ((tid & 31) == 0) sS[tid >> 5] = s;
    __syncthreads();
    float T = sS[0] + sS[1] + sS[2] + sS[3] + sS[4] + sS[5] + sS[6] + sS[7];
    float inv = 1.0f / T;
    #pragma unroll
    for (int i = 0; i < 8; i++) p[tid + i * 256] = v[i] * inv;
}

// -------- GEMM C = act(alpha*A@B + bias) + res --------
// BM=128, BN=64, BK=16, 256 threads, 8x4 per thread.
// Batch: z = zo*inner + zi, offsets = zo*s?o + zi*s?i.  res shares C layout.
__global__ __launch_bounds__(256)
void gemm_nn_kernel(const float* __restrict__ A, int lda, long sAo, long sAi,
                    const float* __restrict__ B, int ldb, long sBo, long sBi,
                    float* __restrict__ C, int ldc, long sCo, long sCi,
                    const float* __restrict__ res,
                    const float* __restrict__ bias,
                    int K, int inner, int act, float alpha)
{
    int zo = blockIdx.z / inner, zi = blockIdx.z - zo * inner;
    A += zo * sAo + (long)zi * sAi;
    B += zo * sBo + (long)zi * sBi;
    long coff = zo * sCo + (long)zi * sCi;
    C += coff;
    if (res) res += coff;

    __shared__ float As[128][17];
    __shared__ float Bs[16][66];
    int tid = threadIdx.x;
    int ty = tid >> 4;
    int bm = blockIdx.y << 7, bn = blockIdx.x << 6;

    int arow = tid >> 1;
    int ak   = (tid & 1) << 3;
    int brow = tid >> 4;
    int bcol = (tid & 15) << 2;

    const float* Aptr = A + (long)(bm + arow) * lda + ak;
    const float* Bptr = B + (long)brow * ldb + bn + bcol;

    float acc[8][4];
    #pragma unroll
    for (int i = 0; i < 8; i++)
        #pragma unroll
        for (int j = 0; j < 4; j++) acc[i][j] = 0.f;

    for (int k0 = 0; k0 < K; k0 += 16) {
        float4 a0 = *(const float4*)(Aptr);
        float4 a1 = *(const float4*)(Aptr + 4);
        float4 bv = *(const float4*)(Bptr);
        As[arow][ak + 0] = a0.x; As[arow][ak + 1] = a0.y;
        As[arow][ak + 2] = a0.z; As[arow][ak + 3] = a0.w;
        As[arow][ak + 4] = a1.x; As[arow][ak + 5] = a1.y;
        As[arow][ak + 6] = a1.z; As[arow][ak + 7] = a1.w;
        Bs[brow][bcol + 0] = bv.x; Bs[brow][bcol + 1] = bv.y;
        Bs[brow][bcol + 2] = bv.z; Bs[brow][bcol + 3] = bv.w;
        __syncthreads();
        #pragma unroll
        for (int k = 0; k < 16; k++) {
            float b0 = Bs[k][bcol + 0], b1 = Bs[k][bcol + 1];
            float b2 = Bs[k][bcol + 2], b3 = Bs[k][bcol + 3];
            #pragma unroll
            for (int i = 0; i < 8; i++) {
                float a = As[(ty << 3) + i][k];
                acc[i][0] += a * b0;
                acc[i][1] += a * b1;
                acc[i][2] += a * b2;
                acc[i][3] += a * b3;
            }
        }
        __syncthreads();
        Aptr += 16;
        Bptr += (long)16 * ldb;
    }

    #pragma unroll
    for (int i = 0; i < 8; i++) {
        long row = bm + (ty << 3) + i;
        int col = bn + bcol;
        float4 v;
        v.x = acc[i][0] * alpha; v.y = acc[i][1] * alpha;
        v.z = acc[i][2] * alpha; v.w = acc[i][3] * alpha;
        if (bias) {
            const float4 bb = *(const float4*)(bias + col);
            v.x += bb.x; v.y += bb.y; v.z += bb.z; v.w += bb.w;
        }
        if (act) {  // SiLU
            v.x = v.x / (1.f + __expf(-v.x));
            v.y = v.y / (1.f + __expf(-v.y));
            v.z = v.z / (1.f + __expf(-v.z));
            v.w = v.w / (1.f + __expf(-v.w));
        }
        if (res) {
            const float4 rr = *(const float4*)(res + row * ldc + col);
            v.x += rr.x; v.y += rr.y; v.z += rr.z; v.w += rr.w;
        }
        *(float4*)(C + row * ldc + col) = v;
    }
}

// -------- GEMM C = alpha * A @ B^T (for scores) --------
__global__ __launch_bounds__(256)
void gemm_nt_kernel(const float* __restrict__ A, int lda, long sAo, long sAi,
                    const float* __restrict__ B, int ldb, long sBo, long sBi,
                    float* __restrict__ C, int ldc, long sCo, long sCi,
                    int K, int inner, float alpha)
{
    int zo = blockIdx.z / inner, zi = blockIdx.z - zo * inner;
    A += zo * sAo + (long)zi * sAi;
    B += zo * sBo + (long)zi * sBi;
    C += zo * sCo + (long)zi * sCi;

    __shared__ float As[128][17];
    __shared__ float Bs[16][66];
    int tid = threadIdx.x;
    int ty = tid >> 4;
    int bm = blockIdx.y << 7, bn = blockIdx.x << 6;

    int arow = tid >> 1;
    int ak   = (tid & 1) << 3;
    int bnr  = tid >> 2;          // B row (= output col n), 0..63
    int bk4  = (tid & 3) << 2;    // k offset within tile
    int bcol = (tid & 15) << 2;   // this thread's output cols

    const float* Aptr = A + (long)(bm + arow) * lda + ak;
    const float* Bptr = B + (long)(bn + bnr) * ldb + bk4;

    float acc[8][4];
    #pragma unroll
    for (int i = 0; i < 8; i++)
        #pragma unroll
        for (int j = 0; j < 4; j++) acc[i][j] = 0.f;

    for (int k0 = 0; k0 < K; k0 += 16) {
        float4 a0 = *(const float4*)(Aptr);
        float4 a1 = *(const float4*)(Aptr + 4);
        float4 bv = *(const float4*)(Bptr);
        As[arow][ak + 0] = a0.x; As[arow][ak + 1] = a0.y;
        As[arow][ak + 2] = a0.z; As[arow][ak + 3] = a0.w;
        As[arow][ak + 4] = a1.x; As[arow][ak + 5] = a1.y;
        As[arow][ak + 6] = a1.z; As[arow][ak + 7] = a1.w;
        Bs[bk4 + 0][bnr] = bv.x;
        Bs[bk4 + 1][bnr] = bv.y;
        Bs[bk4 + 2][bnr] = bv.z;
        Bs[bk4 + 3][bnr] = bv.w;
        __syncthreads();
        #pragma unroll
        for (int k = 0; k < 16; k++) {
            float b0 = Bs[k][bcol + 0], b1 = Bs[k][bcol + 1];
            float b2 = Bs[k][bcol + 2], b3 = Bs[k][bcol + 3];
            #pragma unroll
            for (int i = 0; i < 8; i++) {
                float a = As[(ty << 3) + i][k];
                acc[i][0] += a * b0;
                acc[i][1] += a * b1;
                acc[i][2] += a * b2;
                acc[i][3] += a * b3;
            }
        }
        __syncthreads();
        Aptr += 16;
        Bptr += 16;
    }

    #pragma unroll
    for (int i = 0; i < 8; i++) {
        long row = bm + (ty << 3) + i;
        int col = bn + bcol;
        float4 v;
        v.x = acc[i][0] * alpha; v.y = acc[i][1] * alpha;
        v.z = acc[i][2] * alpha; v.w = acc[i][3] * alpha;
        *(float4*)(C + row * ldc + col) = v;
    }
}

// ---------------- host ----------------
extern "C" void kernel_launch(void* const* d_in, const int* in_sizes, int n_in,
                              void* d_out, int out_size)
{
    const float* x   = (const float*)d_in[0];
    const float* wq  = (const float*)d_in[1];
    const float* wk  = (const float*)d_in[2];
    const float* wv  = (const float*)d_in[3];
    const float* wo  = (const float*)d_in[4];
    const float* bo  = (const float*)d_in[5];
    const float* g1  = (const float*)d_in[6];
    const float* b1  = (const float*)d_in[7];
    const float* g2  = (const float*)d_in[8];
    const float* b2  = (const float*)d_in[9];
    const float* w1  = (const float*)d_in[10];
    const float* bf1 = (const float*)d_in[11];
    const float* w2  = (const float*)d_in[12];
    const float* bf2 = (const float*)d_in[13];
    float* out = (float*)d_out;

    float *h, *q, *k, *v, *att, *x1, *h2, *f1, *sc;
    cudaGetSymbolAddress((void**)&h,   g_h);
    cudaGetSymbolAddress((void**)&q,   g_q);
    cudaGetSymbolAddress((void**)&k,   g_k);
    cudaGetSymbolAddress((void**)&v,   g_v);
    cudaGetSymbolAddress((void**)&att, g_att);
    cudaGetSymbolAddress((void**)&x1,  g_x1);
    cudaGetSymbolAddress((void**)&h2,  g_h2);
    cudaGetSymbolAddress((void**)&f1,  g_f1);
    cudaGetSymbolAddress((void**)&sc,  g_sc);

    const float scale = 0.044194173824159216f;  // 512^-0.5
    const long SNL = 2048L * 512;   // tokens-per-batch * E
    const long SSC = 2048L * 2048;  // scores per (n,h)

    // 1) LN1
    layernorm_kernel<<<MTOK, 128>>>(x, g1, b1, h);

    // 2) QKV projections: [8192,512] @ [512,512]
    dim3 gProj(512 / 64, MTOK / 128, 1);
    gemm_nn_kernel<<<gProj, 256>>>(h, 512, 0, 0, wq, 512, 0, 0, q, 512, 0, 0,
                                   nullptr, nullptr, 512, 1, 0, 1.f);
    gemm_nn_kernel<<<gProj, 256>>>(h, 512, 0, 0, wk, 512, 0, 0, k, 512, 0, 0,
                                   nullptr, nullptr, 512, 1, 0, 1.f);
    gemm_nn_kernel<<<gProj, 256>>>(h, 512, 0, 0, wv, 512, 0, 0, v, 512, 0, 0,
                                   nullptr, nullptr, 512, 1, 0, 1.f);

    // 3) scores[n,h] = scale * q[n,:,h,:] @ k[n,:,h,:]^T  (32 batches)
    dim3 gSc(2048 / 64, 2048 / 128, 32);
    gemm_nt_kernel<<<gSc, 256>>>(q, 512, SNL, 64,
                                 k, 512, SNL, 64,
                                 sc, 2048, 8 * SSC, SSC,
                                 64, 8, scale);

    // 4) softmax over last dim (65536 rows x 2048)
    softmax_kernel<<<65536, 256>>>(sc);

    // 5) att[n,:,h,:] = attn[n,h] @ v[n,:,h,:]   (M=2048, N=64, K=2048)
    dim3 gAv(1, 2048 / 128, 32);
    gemm_nn_kernel<<<gAv, 256>>>(sc, 2048, 8 * SSC, SSC,
                                 v, 512, SNL, 64,
                                 att, 512, SNL, 64,
                                 nullptr, nullptr, 2048, 8, 0, 1.f);

    // 6) O projection + bias + residual(x)
    gemm_nn_kernel<<<gProj, 256>>>(att, 512, 0, 0, wo, 512, 0, 0, x1, 512, 0, 0,
                                   x, bo, 512, 1, 0, 1.f);

    // 7) LN2
    layernorm_kernel<<<MTOK, 128>>>(x1, g2, b2, h2);

    // 8) FFN1 + bias + SiLU: [8192,512] @ [512,2048]
    dim3 gF1(FFDIM / 64, MTOK / 128, 1);
    gemm_nn_kernel<<<gF1, 256>>>(h2, 512, 0, 0, w1, FFDIM, 0, 0, f1, FFDIM, 0, 0,
                                 nullptr, bf1, 512, 1, 1, 1.f);

    // 9) FFN2 + bias + residual(x1) -> out
    gemm_nn_kernel<<<gProj, 256>>>(f1, FFDIM, 0, 0, w2, 512, 0, 0, out, 512, 0, 0,
                                   x1, bf2, FFDIM, 1, 0, 1.f);
}

// round 2
// speedup vs baseline: 2.3339x; 2.3339x over previous
#include <cuda_runtime.h>
#include <cstdint>
#include <math.h>

// N=4, L=2048, E=512, H=8, D=64, FF=2048, tokens M = 8192
#define MTOK 8192
#define EDIM 512
#define FFDIM 2048

// -------- scratch (device globals: allocation-guard safe) --------
__device__ float g_h  [MTOK * EDIM];
__device__ float g_q  [MTOK * EDIM];
__device__ float g_k  [MTOK * EDIM];
__device__ float g_v  [MTOK * EDIM];
__device__ float g_att[MTOK * EDIM];
__device__ float g_x1 [MTOK * EDIM];
__device__ float g_h2 [MTOK * EDIM];
__device__ float g_f1 [MTOK * FFDIM];
__device__ float g_sc [134217728];   // scores: 4*8*2048*2048

// -------- helpers --------
static __device__ __forceinline__ float warpReduceSum(float v) {
    #pragma unroll
    for (int o = 16; o > 0; o >>= 1) v += __shfl_xor_sync(0xffffffffu, v, o);
    return v;
}
static __device__ __forceinline__ float warpReduceMax(float v) {
    #pragma unroll
    for (int o = 16; o > 0; o >>= 1) v = fmaxf(v, __shfl_xor_sync(0xffffffffu, v, o));
    return v;
}
static __device__ __forceinline__ uint32_t f2t(float f) {
    uint32_t r;
    asm("cvt.rna.tf32.f32 %0, %1;" : "=r"(r) : "f"(f));
    return r;
}
static __device__ __forceinline__ void mma_tf32(float* c, const uint32_t* a, const uint32_t* b) {
    asm volatile(
        "mma.sync.aligned.m16n8k8.row.col.f32.tf32.tf32.f32 "
        "{%0,%1,%2,%3}, {%4,%5,%6,%7}, {%8,%9}, {%0,%1,%2,%3};"
        : "+f"(c[0]), "+f"(c[1]), "+f"(c[2]), "+f"(c[3])
        : "r"(a[0]), "r"(a[1]), "r"(a[2]), "r"(a[3]), "r"(b[0]), "r"(b[1]));
}

// -------- LayerNorm --------
__global__ __launch_bounds__(128)
void layernorm_kernel(const float* __restrict__ x, const float* __restrict__ g,
                      const float* __restrict__ b, float* __restrict__ out)
{
    long row = blockIdx.x;
    int tid = threadIdx.x;
    const float4 v = ((const float4*)(x + row * EDIM))[tid];
    float s  = v.x + v.y + v.z + v.w;
    float ss = v.x*v.x + v.y*v.y + v.z*v.z + v.w*v.w;
    s  = warpReduceSum(s);
    ss = warpReduceSum(ss);
    __shared__ float sA[4], sB[4];
    if ((tid & 31) == 0) { sA[tid >> 5] = s; sB[tid >> 5] = ss; }
    __syncthreads();
    float ts  = sA[0] + sA[1] + sA[2] + sA[3];
    float tss = sB[0] + sB[1] + sB[2] + sB[3];
    float mean = ts * (1.0f / 512.0f);
    float var  = tss * (1.0f / 512.0f) - mean * mean;
    float r = rsqrtf(var + 1e-5f);
    const float4 gv = ((const float4*)g)[tid];
    const float4 bv = ((const float4*)b)[tid];
    float4 o;
    o.x = (v.x - mean) * r * gv.x + bv.x;
    o.y = (v.y - mean) * r * gv.y + bv.y;
    o.z = (v.z - mean) * r * gv.z + bv.z;
    o.w = (v.w - mean) * r * gv.w + bv.w;
    ((float4*)(out + row * EDIM))[tid] = o;
}

// -------- row softmax over 2048 columns --------
__global__ __launch_bounds__(256)
void softmax_kernel(float* __restrict__ S)
{
    float* p = S + (long)blockIdx.x * 2048;
    int tid = threadIdx.x;
    float v[8];
    float m = -1e30f;
    #pragma unroll
    for (int i = 0; i < 8; i++) { v[i] = p[tid + i * 256]; m = fmaxf(m, v[i]); }
    m = warpReduceMax(m);
    __shared__ float sM[8], sS[8];
    if ((tid & 31) == 0) sM[tid >> 5] = m;
    __syncthreads();
    float M = sM[0];
    #pragma unroll
    for (int i = 1; i < 8; i++) M = fmaxf(M, sM[i]);
    float s = 0.f;
    #pragma unroll
    for (int i = 0; i < 8; i++) { v[i] = __expf(v[i] - M); s += v[i]; }
    s = warpReduceSum(s);
    if ((tid & 31) == 0) sS[tid >> 5] = s;
    __syncthreads();
    float T = sS[0] + sS[1] + sS[2] + sS[3] + sS[4] + sS[5] + sS[6] + sS[7];
    float inv = 1.0f / T;
    #pragma unroll
    for (int i = 0; i < 8; i++) p[tid + i * 256] = v[i] * inv;
}

// -------- TF32 tensor-core GEMM --------
// C = act(alpha * A @ op(B) + bias) + res
// BM=128, BN template (64/128), BK=16, 256 threads (8 warps, 4m x 2n).
// TRANSB: C[m][n] = sum_k A[m][k] * B[n][k]
// Batch: z = zo*inner + zi, ptr += zo*s?o + zi*s?i.
template<int BN, bool TRANSB>
__global__ __launch_bounds__(256)
void gemm_tc(const float* __restrict__ A, int lda, long sAo, long sAi,
             const float* __restrict__ B, int ldb, long sBo, long sBi,
             float* __restrict__ C, int ldc, long sCo, long sCi,
             const float* __restrict__ res, const float* __restrict__ bias,
             int K, int inner, int act, float alpha)
{
    constexpr int ASTR = 20;                 // 128-row tile, stride 20 (conflict-free frags)
    constexpr int BSTR = TRANSB ? 20 : (BN + 8);
    constexpr int BS_WORDS = TRANSB ? 128 * ASTR : 16 * BSTR;
    constexpr int NT = BN / 16;              // per-warp n tiles (warp covers BN/2 cols)

    __shared__ uint32_t As[2][128 * ASTR];
    __shared__ uint32_t Bs[2][BS_WORDS];

    int zo = blockIdx.z / inner, zi = blockIdx.z - zo * inner;
    A += zo * sAo + (long)zi * sAi;
    B += zo * sBo + (long)zi * sBi;
    long coff = zo * sCo + (long)zi * sCi;
    C += coff;
    if (res) res += coff;

    const int tid  = threadIdx.x;
    const int lane = tid & 31, warp = tid >> 5;
    const int wm = warp & 3, wn = warp >> 2;     // 4 x 2 warp grid
    const int gid = lane >> 2, tig = lane & 3;
    const int bm = blockIdx.y << 7;
    const int bn = blockIdx.x * BN;

    // global load mapping
    const int arow = tid >> 1, akc = (tid & 1) << 3;   // A: 128 rows x 16 k
    const float* Aptr = A + (long)(bm + arow) * lda + akc;
    const float* Bptr;
    int bnrow = 0, bncol = 0;
    if (TRANSB) {
        Bptr = B + (long)(bn + arow) * ldb + akc;       // B rows = out cols
    } else {
        bnrow = tid >> 4;                                // 0..15 (k)
        bncol = (tid & 15) << 2;                         // 0..60
        Bptr = B + (long)bnrow * ldb + bn + bncol;
    }

    float acc[2][NT][4];
    #pragma unroll
    for (int mt = 0; mt < 2; mt++)
        #pragma unroll
        for (int nt = 0; nt < NT; nt++)
            #pragma unroll
            for (int j = 0; j < 4; j++) acc[mt][nt][j] = 0.f;

    // ---- prologue: tile 0 ----
    {
        float4 a0 = *(const float4*)Aptr, a1 = *(const float4*)(Aptr + 4);
        uint4 u0 = { f2t(a0.x), f2t(a0.y), f2t(a0.z), f2t(a0.w) };
        uint4 u1 = { f2t(a1.x), f2t(a1.y), f2t(a1.z), f2t(a1.w) };
        *(uint4*)&As[0][arow * ASTR + akc]     = u0;
        *(uint4*)&As[0][arow * ASTR + akc + 4] = u1;
        if (TRANSB) {
            float4 b0 = *(const float4*)Bptr, b1 = *(const float4*)(Bptr + 4);
            uint4 w0 = { f2t(b0.x), f2t(b0.y), f2t(b0.z), f2t(b0.w) };
            uint4 w1 = { f2t(b1.x), f2t(b1.y), f2t(b1.z), f2t(b1.w) };
            *(uint4*)&Bs[0][arow * BSTR + akc]     = w0;
            *(uint4*)&Bs[0][arow * BSTR + akc + 4] = w1;
        } else {
            float4 b0 = *(const float4*)Bptr;
            uint4 w0 = { f2t(b0.x), f2t(b0.y), f2t(b0.z), f2t(b0.w) };
            *(uint4*)&Bs[0][bnrow * BSTR + bncol] = w0;
            if (BN == 128) {
                float4 b1 = *(const float4*)(Bptr + 64);
                uint4 w1 = { f2t(b1.x), f2t(b1.y), f2t(b1.z), f2t(b1.w) };
                *(uint4*)&Bs[0][bnrow * BSTR + bncol + 64] = w1;
            }
        }
    }
    __syncthreads();

    int buf = 0;
    const int nIter = K >> 4;
    for (int it = 0; it < nIter; ++it) {
        float4 na0, na1, nb0, nb1;
        const bool nx = (it + 1 < nIter);
        if (nx) {
            Aptr += 16;
            na0 = *(const float4*)Aptr; na1 = *(const float4*)(Aptr + 4);
            if (TRANSB) {
                Bptr += 16;
                nb0 = *(const float4*)Bptr; nb1 = *(const float4*)(Bptr + 4);
            } else {
                Bptr += (long)16 * ldb;
                nb0 = *(const float4*)Bptr;
                if (BN == 128) nb1 = *(const float4*)(Bptr + 64);
            }
        }

        const uint32_t* as = As[buf];
        const uint32_t* bs = Bs[buf];
        #pragma unroll
        for (int kk = 0; kk < 2; kk++) {
            const int k0 = kk * 8;
            uint32_t af[2][4];
            #pragma unroll
            for (int mt = 0; mt < 2; mt++) {
                const int r = wm * 32 + mt * 16 + gid;
                af[mt][0] = as[r * ASTR + k0 + tig];
                af[mt][1] = as[(r + 8) * ASTR + k0 + tig];
                af[mt][2] = as[r * ASTR + k0 + tig + 4];
                af[mt][3] = as[(r + 8) * ASTR + k0 + tig + 4];
            }
            uint32_t bf[NT][2];
            #pragma unroll
            for (int nt = 0; nt < NT; nt++) {
                const int n = wn * (BN / 2) + nt * 8 + gid;
                if (TRANSB) {
                    bf[nt][0] = bs[n * BSTR + k0 + tig];
                    bf[nt][1] = bs[n * BSTR + k0 + tig + 4];
                } else {
                    bf[nt][0] = bs[(k0 + tig) * BSTR + n];
                    bf[nt][1] = bs[(k0 + tig + 4) * BSTR + n];
                }
            }
            #pragma unroll
            for (int mt = 0; mt < 2; mt++)
                #pragma unroll
                for (int nt = 0; nt < NT; nt++)
                    mma_tf32(acc[mt][nt], af[mt], bf[nt]);
        }

        if (nx) {
            const int nb = buf ^ 1;
            uint4 u0 = { f2t(na0.x), f2t(na0.y), f2t(na0.z), f2t(na0.w) };
            uint4 u1 = { f2t(na1.x), f2t(na1.y), f2t(na1.z), f2t(na1.w) };
            *(uint4*)&As[nb][arow * ASTR + akc]     = u0;
            *(uint4*)&As[nb][arow * ASTR + akc + 4] = u1;
            if (TRANSB) {
                uint4 w0 = { f2t(nb0.x), f2t(nb0.y), f2t(nb0.z), f2t(nb0.w) };
                uint4 w1 = { f2t(nb1.x), f2t(nb1.y), f2t(nb1.z), f2t(nb1.w) };
                *(uint4*)&Bs[nb][arow * BSTR + akc]     = w0;
                *(uint4*)&Bs[nb][arow * BSTR + akc + 4] = w1;
            } else {
                uint4 w0 = { f2t(nb0.x), f2t(nb0.y), f2t(nb0.z), f2t(nb0.w) };
                *(uint4*)&Bs[nb][bnrow * BSTR + bncol] = w0;
                if (BN == 128) {
                    uint4 w1 = { f2t(nb1.x), f2t(nb1.y), f2t(nb1.z), f2t(nb1.w) };
                    *(uint4*)&Bs[nb][bnrow * BSTR + bncol + 64] = w1;
                }
            }
            __syncthreads();
            buf ^= 1;
        }
    }

    // ---- epilogue ----
    #pragma unroll
    for (int mt = 0; mt < 2; mt++) {
        #pragma unroll
        for (int nt = 0; nt < NT; nt++) {
            const long r0 = bm + wm * 32 + mt * 16 + gid;
            const int  cc = bn + wn * (BN / 2) + nt * 8 + tig * 2;
            float2 bb = make_float2(0.f, 0.f);
            if (bias) bb = *(const float2*)(bias + cc);
            #pragma unroll
            for (int half = 0; half < 2; half++) {
                const long r = r0 + half * 8;
                float vx = acc[mt][nt][half * 2 + 0] * alpha + bb.x;
                float vy = acc[mt][nt][half * 2 + 1] * alpha + bb.y;
                if (act) {
                    vx = vx / (1.f + __expf(-vx));
                    vy = vy / (1.f + __expf(-vy));
                }
                if (res) {
                    const float2 rr = *(const float2*)(res + r * ldc + cc);
                    vx += rr.x; vy += rr.y;
                }
                *(float2*)(C + r * ldc + cc) = make_float2(vx, vy);
            }
        }
    }
}

// ---------------- host ----------------
extern "C" void kernel_launch(void* const* d_in, const int* in_sizes, int n_in,
                              void* d_out, int out_size)
{
    const float* x   = (const float*)d_in[0];
    const float* wq  = (const float*)d_in[1];
    const float* wk  = (const float*)d_in[2];
    const float* wv  = (const float*)d_in[3];
    const float* wo  = (const float*)d_in[4];
    const float* bo  = (const float*)d_in[5];
    const float* g1  = (const float*)d_in[6];
    const float* b1  = (const float*)d_in[7];
    const float* g2  = (const float*)d_in[8];
    const float* b2  = (const float*)d_in[9];
    const float* w1  = (const float*)d_in[10];
    const float* bf1 = (const float*)d_in[11];
    const float* w2  = (const float*)d_in[12];
    const float* bf2 = (const float*)d_in[13];
    float* out = (float*)d_out;

    float *h, *q, *k, *v, *att, *x1, *h2, *f1, *sc;
    cudaGetSymbolAddress((void**)&h,   g_h);
    cudaGetSymbolAddress((void**)&q,   g_q);
    cudaGetSymbolAddress((void**)&k,   g_k);
    cudaGetSymbolAddress((void**)&v,   g_v);
    cudaGetSymbolAddress((void**)&att, g_att);
    cudaGetSymbolAddress((void**)&x1,  g_x1);
    cudaGetSymbolAddress((void**)&h2,  g_h2);
    cudaGetSymbolAddress((void**)&f1,  g_f1);
    cudaGetSymbolAddress((void**)&sc,  g_sc);

    const float scale = 0.044194173824159216f;  // 512^-0.5
    const long SNL = 2048L * 512;
    const long SSC = 2048L * 2048;

    // 1) LN1
    layernorm_kernel<<<MTOK, 128>>>(x, g1, b1, h);

    // 2) QKV projections [8192,512] @ [512,512]
    dim3 gProj(EDIM / 128, MTOK / 128, 1);
    gemm_tc<128, false><<<gProj, 256>>>(h, 512, 0, 0, wq, 512, 0, 0, q, 512, 0, 0,
                                        nullptr, nullptr, 512, 1, 0, 1.f);
    gemm_tc<128, false><<<gProj, 256>>>(h, 512, 0, 0, wk, 512, 0, 0, k, 512, 0, 0,
                                        nullptr, nullptr, 512, 1, 0, 1.f);
    gemm_tc<128, false><<<gProj, 256>>>(h, 512, 0, 0, wv, 512, 0, 0, v, 512, 0, 0,
                                        nullptr, nullptr, 512, 1, 0, 1.f);

    // 3) scores = scale * q @ k^T per (n,h): M=N=2048, K=64, 32 batches
    dim3 gSc(2048 / 128, 2048 / 128, 32);
    gemm_tc<128, true><<<gSc, 256>>>(q, 512, SNL, 64,
                                     k, 512, SNL, 64,
                                     sc, 2048, 8 * SSC, SSC,
                                     nullptr, nullptr, 64, 8, 0, scale);

    // 4) softmax (65536 rows x 2048)
    softmax_kernel<<<65536, 256>>>(sc);

    // 5) att = attn @ v per (n,h): M=2048, N=64, K=2048
    dim3 gAv(1, 2048 / 128, 32);
    gemm_tc<64, false><<<gAv, 256>>>(sc, 2048, 8 * SSC, SSC,
                                     v, 512, SNL, 64,
                                     att, 512, SNL, 64,
                                     nullptr, nullptr, 2048, 8, 0, 1.f);

    // 6) O projection + bias + residual(x)
    gemm_tc<128, false><<<gProj, 256>>>(att, 512, 0, 0, wo, 512, 0, 0, x1, 512, 0, 0,
                                        x, bo, 512, 1, 0, 1.f);

    // 7) LN2
    layernorm_kernel<<<MTOK, 128>>>(x1, g2, b2, h2);

    // 8) FFN1 + bias + SiLU: [8192,512] @ [512,2048]
    dim3 gF1(FFDIM / 128, MTOK / 128, 1);
    gemm_tc<128, false><<<gF1, 256>>>(h2, 512, 0, 0, w1, FFDIM, 0, 0, f1, FFDIM, 0, 0,
                                      nullptr, bf1, 512, 1, 1, 1.f);

    // 9) FFN2 + bias + residual(x1) -> out
    gemm_tc<128, false><<<gProj, 256>>>(f1, FFDIM, 0, 0, w2, 512, 0, 0, out, 512, 0, 0,
                                        x1, bf2, FFDIM, 1, 0, 1.f);
}

// round 3
// speedup vs baseline: 3.3292x; 1.4265x over previous
#include <cuda_runtime.h>
#include <cstdint>
#include <math.h>

// N=4, L=2048, E=512, H=8, D=64, FF=2048, tokens M = 8192
#define MTOK 8192
#define EDIM 512
#define FFDIM 2048

// -------- scratch (device globals: allocation-guard safe) --------
__device__ float g_h  [MTOK * EDIM];
__device__ float g_q  [MTOK * EDIM];
__device__ float g_k  [MTOK * EDIM];
__device__ float g_v  [MTOK * EDIM];
__device__ float g_att[MTOK * EDIM];
__device__ float g_x1 [MTOK * EDIM];
__device__ float g_h2 [MTOK * EDIM];
__device__ float g_f1 [MTOK * FFDIM];

// -------- helpers --------
static __device__ __forceinline__ float warpReduceSum(float v) {
    #pragma unroll
    for (int o = 16; o > 0; o >>= 1) v += __shfl_xor_sync(0xffffffffu, v, o);
    return v;
}
static __device__ __forceinline__ uint32_t f2t(float f) {
    uint32_t r;
    asm("cvt.rna.tf32.f32 %0, %1;" : "=r"(r) : "f"(f));
    return r;
}
static __device__ __forceinline__ void mma_tf32(float* c, const uint32_t* a, const uint32_t* b) {
    asm volatile(
        "mma.sync.aligned.m16n8k8.row.col.f32.tf32.tf32.f32 "
        "{%0,%1,%2,%3}, {%4,%5,%6,%7}, {%8,%9}, {%0,%1,%2,%3};"
        : "+f"(c[0]), "+f"(c[1]), "+f"(c[2]), "+f"(c[3])
        : "r"(a[0]), "r"(a[1]), "r"(a[2]), "r"(a[3]), "r"(b[0]), "r"(b[1]));
}

// -------- LayerNorm --------
__global__ __launch_bounds__(128)
void layernorm_kernel(const float* __restrict__ x, const float* __restrict__ g,
                      const float* __restrict__ b, float* __restrict__ out)
{
    long row = blockIdx.x;
    int tid = threadIdx.x;
    const float4 v = ((const float4*)(x + row * EDIM))[tid];
    float s  = v.x + v.y + v.z + v.w;
    float ss = v.x*v.x + v.y*v.y + v.z*v.z + v.w*v.w;
    s  = warpReduceSum(s);
    ss = warpReduceSum(ss);
    __shared__ float sA[4], sB[4];
    if ((tid & 31) == 0) { sA[tid >> 5] = s; sB[tid >> 5] = ss; }
    __syncthreads();
    float ts  = sA[0] + sA[1] + sA[2] + sA[3];
    float tss = sB[0] + sB[1] + sB[2] + sB[3];
    float mean = ts * (1.0f / 512.0f);
    float var  = tss * (1.0f / 512.0f) - mean * mean;
    float r = rsqrtf(var + 1e-5f);
    const float4 gv = ((const float4*)g)[tid];
    const float4 bv = ((const float4*)b)[tid];
    float4 o;
    o.x = (v.x - mean) * r * gv.x + bv.x;
    o.y = (v.y - mean) * r * gv.y + bv.y;
    o.z = (v.z - mean) * r * gv.z + bv.z;
    o.w = (v.w - mean) * r * gv.w + bv.w;
    ((float4*)(out + row * EDIM))[tid] = o;
}

// -------- Fused flash attention (tf32 tensor cores) --------
// Grid: (16 q-tiles, 32 (n,h)). 256 threads = 8 warps; warp w owns Q rows
// [w*16, w*16+16). Q held in A-fragments; K/V tiles of 128 keys staged in smem.
// Online softmax; P staged through per-warp-private smem strip as tf32.
#define QSTR 68   // Q/K smem stride (words): gid*4+tig conflict-free
#define VSTR 72   // V smem stride: tig*8+gid conflict-free
#define PSTR 132
#define FLASH_SMEM ((128*QSTR + 128*VSTR + 128*PSTR) * 4)

__global__ __launch_bounds__(256, 1)
void flash_attn(const float* __restrict__ Qm, const float* __restrict__ Km,
                const float* __restrict__ Vm, float* __restrict__ Om)
{
    extern __shared__ uint32_t dsm[];
    uint32_t* sK = dsm;                        // [128][QSTR]
    uint32_t* sV = dsm + 128 * QSTR;           // [128][VSTR] (stages Q first)
    uint32_t* sP = dsm + 128 * (QSTR + VSTR);  // [128][PSTR] tf32 P

    const int nh = blockIdx.y;                 // n*8 + h
    const long base = (long)(nh >> 3) * 2048 * 512 + (nh & 7) * 64;
    const int q0 = blockIdx.x << 7;

    const int tid = threadIdx.x, lane = tid & 31, w = tid >> 5;
    const int gid = lane >> 2, tig = lane & 3;
    const int lrow = tid >> 4;                 // loader: 16 rows/pass
    const int lc4  = (tid & 15) << 2;          // 4 cols/thread

    const float scale = 0.044194173824159216f; // 512^-0.5

    // ---- stage Q (scaled) into sV, then pull A-fragments ----
    #pragma unroll
    for (int p = 0; p < 8; p++) {
        const int r = p * 16 + lrow;
        const float4 qv = *(const float4*)(Qm + base + (long)(q0 + r) * 512 + lc4);
        uint4 u = { f2t(qv.x * scale), f2t(qv.y * scale),
                    f2t(qv.z * scale), f2t(qv.w * scale) };
        *(uint4*)&sV[r * QSTR + lc4] = u;
    }
    __syncthreads();
    uint32_t aq[8][4];
    {
        const int qr = w * 16 + gid;
        #pragma unroll
        for (int kt = 0; kt < 8; kt++) {
            aq[kt][0] = sV[qr * QSTR + kt * 8 + tig];
            aq[kt][1] = sV[(qr + 8) * QSTR + kt * 8 + tig];
            aq[kt][2] = sV[qr * QSTR + kt * 8 + tig + 4];
            aq[kt][3] = sV[(qr + 8) * QSTR + kt * 8 + tig + 4];
        }
    }

    float m0 = -1e30f, m1 = -1e30f, l0 = 0.f, l1 = 0.f;
    float oacc[8][4];
    #pragma unroll
    for (int nt = 0; nt < 8; nt++)
        #pragma unroll
        for (int j = 0; j < 4; j++) oacc[nt][j] = 0.f;

    const int prow0 = (w * 16 + gid) * PSTR;
    const int prow1 = (w * 16 + gid + 8) * PSTR;

    for (int j = 0; j < 16; j++) {
        __syncthreads();   // prior-tile reads of sK/sV done (and Q frags pulled)
        const int kb = j << 7;
        #pragma unroll
        for (int p = 0; p < 8; p++) {
            const int r = p * 16 + lrow;
            const float4 kv = *(const float4*)(Km + base + (long)(kb + r) * 512 + lc4);
            const float4 vv = *(const float4*)(Vm + base + (long)(kb + r) * 512 + lc4);
            uint4 uk = { f2t(kv.x), f2t(kv.y), f2t(kv.z), f2t(kv.w) };
            uint4 uv = { f2t(vv.x), f2t(vv.y), f2t(vv.z), f2t(vv.w) };
            *(uint4*)&sK[r * QSTR + lc4] = uk;
            *(uint4*)&sV[r * VSTR + lc4] = uv;
        }
        __syncthreads();

        // ---- S = Q @ K^T (scaled) ----
        float sacc[16][4];
        #pragma unroll
        for (int nt = 0; nt < 16; nt++)
            #pragma unroll
            for (int q = 0; q < 4; q++) sacc[nt][q] = 0.f;
        #pragma unroll
        for (int kt = 0; kt < 8; kt++) {
            #pragma unroll
            for (int nt = 0; nt < 16; nt++) {
                uint32_t bk[2];
                bk[0] = sK[(nt * 8 + gid) * QSTR + kt * 8 + tig];
                bk[1] = sK[(nt * 8 + gid) * QSTR + kt * 8 + tig + 4];
                mma_tf32(sacc[nt], aq[kt], bk);
            }
        }

        // ---- online softmax ----
        float rm0 = sacc[0][0], rm1 = sacc[0][2];
        #pragma unroll
        for (int nt = 0; nt < 16; nt++) {
            rm0 = fmaxf(rm0, fmaxf(sacc[nt][0], sacc[nt][1]));
            rm1 = fmaxf(rm1, fmaxf(sacc[nt][2], sacc[nt][3]));
        }
        rm0 = fmaxf(rm0, __shfl_xor_sync(0xffffffffu, rm0, 1));
        rm0 = fmaxf(rm0, __shfl_xor_sync(0xffffffffu, rm0, 2));
        rm1 = fmaxf(rm1, __shfl_xor_sync(0xffffffffu, rm1, 1));
        rm1 = fmaxf(rm1, __shfl_xor_sync(0xffffffffu, rm1, 2));
        const float mn0 = fmaxf(m0, rm0), mn1 = fmaxf(m1, rm1);
        const float f0 = __expf(m0 - mn0), f1 = __expf(m1 - mn1);
        m0 = mn0; m1 = mn1;

        float rs0 = 0.f, rs1 = 0.f;
        #pragma unroll
        for (int nt = 0; nt < 16; nt++) {
            const float p0 = __expf(sacc[nt][0] - mn0);
            const float p1 = __expf(sacc[nt][1] - mn0);
            const float p2 = __expf(sacc[nt][2] - mn1);
            const float p3 = __expf(sacc[nt][3] - mn1);
            rs0 += p0 + p1; rs1 += p2 + p3;
            uint2 w0 = { f2t(p0), f2t(p1) };
            uint2 w1 = { f2t(p2), f2t(p3) };
            *(uint2*)&sP[prow0 + nt * 8 + tig * 2] = w0;
            *(uint2*)&sP[prow1 + nt * 8 + tig * 2] = w1;
        }
        rs0 += __shfl_xor_sync(0xffffffffu, rs0, 1);
        rs0 += __shfl_xor_sync(0xffffffffu, rs0, 2);
        rs1 += __shfl_xor_sync(0xffffffffu, rs1, 1);
        rs1 += __shfl_xor_sync(0xffffffffu, rs1, 2);
        l0 = l0 * f0 + rs0;
        l1 = l1 * f1 + rs1;

        #pragma unroll
        for (int nt = 0; nt < 8; nt++) {
            oacc[nt][0] *= f0; oacc[nt][1] *= f0;
            oacc[nt][2] *= f1; oacc[nt][3] *= f1;
        }
        __syncwarp();

        // ---- O += P @ V ----
        #pragma unroll
        for (int kt = 0; kt < 16; kt++) {
            uint32_t ap[4];
            ap[0] = sP[prow0 + kt * 8 + tig];
            ap[1] = sP[prow1 + kt * 8 + tig];
            ap[2] = sP[prow0 + kt * 8 + tig + 4];
            ap[3] = sP[prow1 + kt * 8 + tig + 4];
            #pragma unroll
            for (int nt = 0; nt < 8; nt++) {
                uint32_t bv[2];
                bv[0] = sV[(kt * 8 + tig) * VSTR + nt * 8 + gid];
                bv[1] = sV[(kt * 8 + tig + 4) * VSTR + nt * 8 + gid];
                mma_tf32(oacc[nt], ap, bv);
            }
        }
    }

    // ---- epilogue: normalize and write ----
    const float invl0 = 1.f / l0, invl1 = 1.f / l1;
    const long orow0 = base + (long)(q0 + w * 16 + gid) * 512;
    const long orow1 = orow0 + 8L * 512;
    #pragma unroll
    for (int nt = 0; nt < 8; nt++) {
        const int cc = nt * 8 + tig * 2;
        *(float2*)(Om + orow0 + cc) = make_float2(oacc[nt][0] * invl0, oacc[nt][1] * invl0);
        *(float2*)(Om + orow1 + cc) = make_float2(oacc[nt][2] * invl1, oacc[nt][3] * invl1);
    }
}

// -------- TF32 tensor-core GEMM (dense layers) --------
// C = act(alpha * A @ B + bias) + res ; BM=128, BN=128, BK=16, 256 threads.
__global__ __launch_bounds__(256)
void gemm_tc(const float* __restrict__ A, int lda,
             const float* __restrict__ B, int ldb,
             float* __restrict__ C, int ldc,
             const float* __restrict__ res, const float* __restrict__ bias,
             int K, int act)
{
    constexpr int BN = 128;
    constexpr int ASTR = 20;
    constexpr int BSTR = BN + 8;
    constexpr int NT = BN / 16;

    __shared__ uint32_t As[2][128 * ASTR];
    __shared__ uint32_t Bs[2][16 * BSTR];

    const int tid  = threadIdx.x;
    const int lane = tid & 31, warp = tid >> 5;
    const int wm = warp & 3, wn = warp >> 2;
    const int gid = lane >> 2, tig = lane & 3;
    const int bm = blockIdx.y << 7;
    const int bn = blockIdx.x * BN;

    const int arow = tid >> 1, akc = (tid & 1) << 3;
    const float* Aptr = A + (long)(bm + arow) * lda + akc;
    const int bnrow = tid >> 4;
    const int bncol = (tid & 15) << 2;
    const float* Bptr = B + (long)bnrow * ldb + bn + bncol;

    float acc[2][NT][4];
    #pragma unroll
    for (int mt = 0; mt < 2; mt++)
        #pragma unroll
        for (int nt = 0; nt < NT; nt++)
            #pragma unroll
            for (int j = 0; j < 4; j++) acc[mt][nt][j] = 0.f;

    {
        float4 a0 = *(const float4*)Aptr, a1 = *(const float4*)(Aptr + 4);
        uint4 u0 = { f2t(a0.x), f2t(a0.y), f2t(a0.z), f2t(a0.w) };
        uint4 u1 = { f2t(a1.x), f2t(a1.y), f2t(a1.z), f2t(a1.w) };
        *(uint4*)&As[0][arow * ASTR + akc]     = u0;
        *(uint4*)&As[0][arow * ASTR + akc + 4] = u1;
        float4 b0 = *(const float4*)Bptr;
        float4 b1 = *(const float4*)(Bptr + 64);
        uint4 w0 = { f2t(b0.x), f2t(b0.y), f2t(b0.z), f2t(b0.w) };
        uint4 w1 = { f2t(b1.x), f2t(b1.y), f2t(b1.z), f2t(b1.w) };
        *(uint4*)&Bs[0][bnrow * BSTR + bncol]      = w0;
        *(uint4*)&Bs[0][bnrow * BSTR + bncol + 64] = w1;
    }
    __syncthreads();

    int buf = 0;
    const int nIter = K >> 4;
    for (int it = 0; it < nIter; ++it) {
        float4 na0, na1, nb0, nb1;
        const bool nx = (it + 1 < nIter);
        if (nx) {
            Aptr += 16;
            na0 = *(const float4*)Aptr; na1 = *(const float4*)(Aptr + 4);
            Bptr += (long)16 * ldb;
            nb0 = *(const float4*)Bptr; nb1 = *(const float4*)(Bptr + 64);
        }

        const uint32_t* as = As[buf];
        const uint32_t* bs = Bs[buf];
        #pragma unroll
        for (int kk = 0; kk < 2; kk++) {
            const int k0 = kk * 8;
            uint32_t af[2][4];
            #pragma unroll
            for (int mt = 0; mt < 2; mt++) {
                const int r = wm * 32 + mt * 16 + gid;
                af[mt][0] = as[r * ASTR + k0 + tig];
                af[mt][1] = as[(r + 8) * ASTR + k0 + tig];
                af[mt][2] = as[r * ASTR + k0 + tig + 4];
                af[mt][3] = as[(r + 8) * ASTR + k0 + tig + 4];
            }
            uint32_t bf[NT][2];
            #pragma unroll
            for (int nt = 0; nt < NT; nt++) {
                const int n = wn * (BN / 2) + nt * 8 + gid;
                bf[nt][0] = bs[(k0 + tig) * BSTR + n];
                bf[nt][1] = bs[(k0 + tig + 4) * BSTR + n];
            }
            #pragma unroll
            for (int mt = 0; mt < 2; mt++)
                #pragma unroll
                for (int nt = 0; nt < NT; nt++)
                    mma_tf32(acc[mt][nt], af[mt], bf[nt]);
        }

        if (nx) {
            const int nb = buf ^ 1;
            uint4 u0 = { f2t(na0.x), f2t(na0.y), f2t(na0.z), f2t(na0.w) };
            uint4 u1 = { f2t(na1.x), f2t(na1.y), f2t(na1.z), f2t(na1.w) };
            *(uint4*)&As[nb][arow * ASTR + akc]     = u0;
            *(uint4*)&As[nb][arow * ASTR + akc + 4] = u1;
            uint4 w0 = { f2t(nb0.x), f2t(nb0.y), f2t(nb0.z), f2t(nb0.w) };
            uint4 w1 = { f2t(nb1.x), f2t(nb1.y), f2t(nb1.z), f2t(nb1.w) };
            *(uint4*)&Bs[nb][bnrow * BSTR + bncol]      = w0;
            *(uint4*)&Bs[nb][bnrow * BSTR + bncol + 64] = w1;
            __syncthreads();
            buf ^= 1;
        }
    }

    #pragma unroll
    for (int mt = 0; mt < 2; mt++) {
        #pragma unroll
        for (int nt = 0; nt < NT; nt++) {
            const long r0 = bm + wm * 32 + mt * 16 + gid;
            const int  cc = bn + wn * (BN / 2) + nt * 8 + tig * 2;
            float2 bb = make_float2(0.f, 0.f);
            if (bias) bb = *(const float2*)(bias + cc);
            #pragma unroll
            for (int half = 0; half < 2; half++) {
                const long r = r0 + half * 8;
                float vx = acc[mt][nt][half * 2 + 0] + bb.x;
                float vy = acc[mt][nt][half * 2 + 1] + bb.y;
                if (act) {
                    vx = vx / (1.f + __expf(-vx));
                    vy = vy / (1.f + __expf(-vy));
                }
                if (res) {
                    const float2 rr = *(const float2*)(res + r * ldc + cc);
                    vx += rr.x; vy += rr.y;
                }
                *(float2*)(C + r * ldc + cc) = make_float2(vx, vy);
            }
        }
    }
}

// ---------------- host ----------------
extern "C" void kernel_launch(void* const* d_in, const int* in_sizes, int n_in,
                              void* d_out, int out_size)
{
    const float* x   = (const float*)d_in[0];
    const float* wq  = (const float*)d_in[1];
    const float* wk  = (const float*)d_in[2];
    const float* wv  = (const float*)d_in[3];
    const float* wo  = (const float*)d_in[4];
    const float* bo  = (const float*)d_in[5];
    const float* g1  = (const float*)d_in[6];
    const float* b1  = (const float*)d_in[7];
    const float* g2  = (const float*)d_in[8];
    const float* b2  = (const float*)d_in[9];
    const float* w1  = (const float*)d_in[10];
    const float* bf1 = (const float*)d_in[11];
    const float* w2  = (const float*)d_in[12];
    const float* bf2 = (const float*)d_in[13];
    float* out = (float*)d_out;

    float *h, *q, *k, *v, *att, *x1, *h2, *f1;
    cudaGetSymbolAddress((void**)&h,   g_h);
    cudaGetSymbolAddress((void**)&q,   g_q);
    cudaGetSymbolAddress((void**)&k,   g_k);
    cudaGetSymbolAddress((void**)&v,   g_v);
    cudaGetSymbolAddress((void**)&att, g_att);
    cudaGetSymbolAddress((void**)&x1,  g_x1);
    cudaGetSymbolAddress((void**)&h2,  g_h2);
    cudaGetSymbolAddress((void**)&f1,  g_f1);

    static bool attr_done = false;
    if (!attr_done) {
        cudaFuncSetAttribute(flash_attn, cudaFuncAttributeMaxDynamicSharedMemorySize,
                             FLASH_SMEM);
        attr_done = true;
    }

    // 1) LN1
    layernorm_kernel<<<MTOK, 128>>>(x, g1, b1, h);

    // 2) QKV projections [8192,512] @ [512,512]
    dim3 gProj(EDIM / 128, MTOK / 128);
    gemm_tc<<<gProj, 256>>>(h, 512, wq, 512, q, 512, nullptr, nullptr, 512, 0);
    gemm_tc<<<gProj, 256>>>(h, 512, wk, 512, k, 512, nullptr, nullptr, 512, 0);
    gemm_tc<<<gProj, 256>>>(h, 512, wv, 512, v, 512, nullptr, nullptr, 512, 0);

    // 3-5) fused flash attention -> att
    flash_attn<<<dim3(16, 32), 256, FLASH_SMEM>>>(q, k, v, att);

    // 6) O projection + bias + residual(x)
    gemm_tc<<<gProj, 256>>>(att, 512, wo, 512, x1, 512, x, bo, 512, 0);

    // 7) LN2
    layernorm_kernel<<<MTOK, 128>>>(x1, g2, b2, h2);

    // 8) FFN1 + bias + SiLU
    dim3 gF1(FFDIM / 128, MTOK / 128);
    gemm_tc<<<gF1, 256>>>(h2, 512, w1, FFDIM, f1, FFDIM, nullptr, bf1, 512, 1);

    // 9) FFN2 + bias + residual(x1) -> out
    gemm_tc<<<gProj, 256>>>(f1, FFDIM, w2, 512, out, 512, x1, bf2, FFDIM, 0);
}

// round 4
// speedup vs baseline: 3.4921x; 1.0489x over previous
#include <cuda_runtime.h>
#include <cstdint>
#include <math.h>

// N=4, L=2048, E=512, H=8, D=64, FF=2048, tokens M = 8192
#define MTOK 8192
#define EDIM 512
#define FFDIM 2048

// -------- scratch (device globals: allocation-guard safe) --------
__device__ float g_h  [MTOK * EDIM];
__device__ float g_q  [MTOK * EDIM];
__device__ float g_k  [MTOK * EDIM];
__device__ float g_v  [MTOK * EDIM];
__device__ float g_att[MTOK * EDIM];
__device__ float g_x1 [MTOK * EDIM];
__device__ float g_h2 [MTOK * EDIM];
__device__ float g_f1 [MTOK * FFDIM];

// -------- helpers --------
static __device__ __forceinline__ float warpReduceSum(float v) {
    #pragma unroll
    for (int o = 16; o > 0; o >>= 1) v += __shfl_xor_sync(0xffffffffu, v, o);
    return v;
}
static __device__ __forceinline__ uint32_t f2t(float f) {
    uint32_t r;
    asm("cvt.rna.tf32.f32 %0, %1;" : "=r"(r) : "f"(f));
    return r;
}
static __device__ __forceinline__ void mma_tf32(float* c, const uint32_t* a, const uint32_t* b) {
    asm volatile(
        "mma.sync.aligned.m16n8k8.row.col.f32.tf32.tf32.f32 "
        "{%0,%1,%2,%3}, {%4,%5,%6,%7}, {%8,%9}, {%0,%1,%2,%3};"
        : "+f"(c[0]), "+f"(c[1]), "+f"(c[2]), "+f"(c[3])
        : "r"(a[0]), "r"(a[1]), "r"(a[2]), "r"(a[3]), "r"(b[0]), "r"(b[1]));
}

// -------- LayerNorm --------
__global__ __launch_bounds__(128)
void layernorm_kernel(const float* __restrict__ x, const float* __restrict__ g,
                      const float* __restrict__ b, float* __restrict__ out)
{
    long row = blockIdx.x;
    int tid = threadIdx.x;
    const float4 v = ((const float4*)(x + row * EDIM))[tid];
    float s  = v.x + v.y + v.z + v.w;
    float ss = v.x*v.x + v.y*v.y + v.z*v.z + v.w*v.w;
    s  = warpReduceSum(s);
    ss = warpReduceSum(ss);
    __shared__ float sA[4], sB[4];
    if ((tid & 31) == 0) { sA[tid >> 5] = s; sB[tid >> 5] = ss; }
    __syncthreads();
    float ts  = sA[0] + sA[1] + sA[2] + sA[3];
    float tss = sB[0] + sB[1] + sB[2] + sB[3];
    float mean = ts * (1.0f / 512.0f);
    float var  = tss * (1.0f / 512.0f) - mean * mean;
    float r = rsqrtf(var + 1e-5f);
    const float4 gv = ((const float4*)g)[tid];
    const float4 bv = ((const float4*)b)[tid];
    float4 o;
    o.x = (v.x - mean) * r * gv.x + bv.x;
    o.y = (v.y - mean) * r * gv.y + bv.y;
    o.z = (v.z - mean) * r * gv.z + bv.z;
    o.w = (v.w - mean) * r * gv.w + bv.w;
    ((float4*)(out + row * EDIM))[tid] = o;
}

// -------- Fused flash attention (tf32, 64-key tiles, 2 CTAs/SM) --------
// Grid: (16 q-tiles, 32 (n,h)). 256 threads = 8 warps; warp w owns Q rows
// [w*16, w*16+16). Q in A-fragments; 64-key K/V tiles in smem; online softmax;
// P staged per-warp through smem.
#define QSTR 68   // K smem stride (words)
#define VSTR 72   // V smem stride
#define PSTR 68   // P smem stride (64 cols + 4 pad)
#define FLASH_SMEM ((64*QSTR + 64*VSTR + 128*PSTR) * 4)

__global__ __launch_bounds__(256, 2)
void flash_attn(const float* __restrict__ Qm, const float* __restrict__ Km,
                const float* __restrict__ Vm, float* __restrict__ Om)
{
    extern __shared__ uint32_t dsm[];
    uint32_t* sK = dsm;                       // [64][QSTR]
    uint32_t* sV = dsm + 64 * QSTR;           // [64][VSTR]
    uint32_t* sP = dsm + 64 * (QSTR + VSTR);  // [128][PSTR]; stages Q first

    const int nh = blockIdx.y;
    const long base = (long)(nh >> 3) * 2048 * 512 + (nh & 7) * 64;
    const int q0 = blockIdx.x << 7;

    const int tid = threadIdx.x, lane = tid & 31, w = tid >> 5;
    const int gid = lane >> 2, tig = lane & 3;
    const int lrow = tid >> 4;                // loader: 16 rows/pass
    const int lc4  = (tid & 15) << 2;

    const float scale = 0.044194173824159216f; // 512^-0.5

    // ---- stage Q (scaled) into sP, pull A-fragments ----
    #pragma unroll
    for (int p = 0; p < 8; p++) {
        const int r = p * 16 + lrow;
        const float4 qv = *(const float4*)(Qm + base + (long)(q0 + r) * 512 + lc4);
        uint4 u = { f2t(qv.x * scale), f2t(qv.y * scale),
                    f2t(qv.z * scale), f2t(qv.w * scale) };
        *(uint4*)&sP[r * PSTR + lc4] = u;
    }
    __syncthreads();
    uint32_t aq[8][4];
    {
        const int qr = w * 16 + gid;
        #pragma unroll
        for (int kt = 0; kt < 8; kt++) {
            aq[kt][0] = sP[qr * PSTR + kt * 8 + tig];
            aq[kt][1] = sP[(qr + 8) * PSTR + kt * 8 + tig];
            aq[kt][2] = sP[qr * PSTR + kt * 8 + tig + 4];
            aq[kt][3] = sP[(qr + 8) * PSTR + kt * 8 + tig + 4];
        }
    }

    float m0 = -1e30f, m1 = -1e30f, l0 = 0.f, l1 = 0.f;
    float oacc[8][4];
    #pragma unroll
    for (int nt = 0; nt < 8; nt++)
        #pragma unroll
        for (int j = 0; j < 4; j++) oacc[nt][j] = 0.f;

    const int prow0 = (w * 16 + gid) * PSTR;
    const int prow1 = (w * 16 + gid + 8) * PSTR;

    for (int j = 0; j < 32; j++) {
        __syncthreads();   // prior-tile smem reads complete
        const int kb = j << 6;
        #pragma unroll
        for (int p = 0; p < 4; p++) {
            const int r = p * 16 + lrow;
            const float4 kv = *(const float4*)(Km + base + (long)(kb + r) * 512 + lc4);
            const float4 vv = *(const float4*)(Vm + base + (long)(kb + r) * 512 + lc4);
            uint4 uk = { f2t(kv.x), f2t(kv.y), f2t(kv.z), f2t(kv.w) };
            uint4 uv = { f2t(vv.x), f2t(vv.y), f2t(vv.z), f2t(vv.w) };
            *(uint4*)&sK[r * QSTR + lc4] = uk;
            *(uint4*)&sV[r * VSTR + lc4] = uv;
        }
        __syncthreads();

        // ---- S = Q @ K^T ----
        float sacc[8][4];
        #pragma unroll
        for (int nt = 0; nt < 8; nt++)
            #pragma unroll
            for (int q = 0; q < 4; q++) sacc[nt][q] = 0.f;
        #pragma unroll
        for (int kt = 0; kt < 8; kt++) {
            #pragma unroll
            for (int nt = 0; nt < 8; nt++) {
                uint32_t bk[2];
                bk[0] = sK[(nt * 8 + gid) * QSTR + kt * 8 + tig];
                bk[1] = sK[(nt * 8 + gid) * QSTR + kt * 8 + tig + 4];
                mma_tf32(sacc[nt], aq[kt], bk);
            }
        }

        // ---- online softmax ----
        float rm0 = sacc[0][0], rm1 = sacc[0][2];
        #pragma unroll
        for (int nt = 0; nt < 8; nt++) {
            rm0 = fmaxf(rm0, fmaxf(sacc[nt][0], sacc[nt][1]));
            rm1 = fmaxf(rm1, fmaxf(sacc[nt][2], sacc[nt][3]));
        }
        rm0 = fmaxf(rm0, __shfl_xor_sync(0xffffffffu, rm0, 1));
        rm0 = fmaxf(rm0, __shfl_xor_sync(0xffffffffu, rm0, 2));
        rm1 = fmaxf(rm1, __shfl_xor_sync(0xffffffffu, rm1, 1));
        rm1 = fmaxf(rm1, __shfl_xor_sync(0xffffffffu, rm1, 2));
        const float mn0 = fmaxf(m0, rm0), mn1 = fmaxf(m1, rm1);
        const float f0 = __expf(m0 - mn0), f1 = __expf(m1 - mn1);
        m0 = mn0; m1 = mn1;

        float rs0 = 0.f, rs1 = 0.f;
        #pragma unroll
        for (int nt = 0; nt < 8; nt++) {
            const float p0 = __expf(sacc[nt][0] - mn0);
            const float p1 = __expf(sacc[nt][1] - mn0);
            const float p2 = __expf(sacc[nt][2] - mn1);
            const float p3 = __expf(sacc[nt][3] - mn1);
            rs0 += p0 + p1; rs1 += p2 + p3;
            uint2 w0 = { f2t(p0), f2t(p1) };
            uint2 w1 = { f2t(p2), f2t(p3) };
            *(uint2*)&sP[prow0 + nt * 8 + tig * 2] = w0;
            *(uint2*)&sP[prow1 + nt * 8 + tig * 2] = w1;
        }
        rs0 += __shfl_xor_sync(0xffffffffu, rs0, 1);
        rs0 += __shfl_xor_sync(0xffffffffu, rs0, 2);
        rs1 += __shfl_xor_sync(0xffffffffu, rs1, 1);
        rs1 += __shfl_xor_sync(0xffffffffu, rs1, 2);
        l0 = l0 * f0 + rs0;
        l1 = l1 * f1 + rs1;

        #pragma unroll
        for (int nt = 0; nt < 8; nt++) {
            oacc[nt][0] *= f0; oacc[nt][1] *= f0;
            oacc[nt][2] *= f1; oacc[nt][3] *= f1;
        }
        __syncwarp();

        // ---- O += P @ V ----
        #pragma unroll
        for (int kt = 0; kt < 8; kt++) {
            uint32_t ap[4];
            ap[0] = sP[prow0 + kt * 8 + tig];
            ap[1] = sP[prow1 + kt * 8 + tig];
            ap[2] = sP[prow0 + kt * 8 + tig + 4];
            ap[3] = sP[prow1 + kt * 8 + tig + 4];
            #pragma unroll
            for (int nt = 0; nt < 8; nt++) {
                uint32_t bv[2];
                bv[0] = sV[(kt * 8 + tig) * VSTR + nt * 8 + gid];
                bv[1] = sV[(kt * 8 + tig + 4) * VSTR + nt * 8 + gid];
                mma_tf32(oacc[nt], ap, bv);
            }
        }
    }

    // ---- epilogue ----
    const float invl0 = 1.f / l0, invl1 = 1.f / l1;
    const long orow0 = base + (long)(q0 + w * 16 + gid) * 512;
    const long orow1 = orow0 + 8L * 512;
    #pragma unroll
    for (int nt = 0; nt < 8; nt++) {
        const int cc = nt * 8 + tig * 2;
        *(float2*)(Om + orow0 + cc) = make_float2(oacc[nt][0] * invl0, oacc[nt][1] * invl0);
        *(float2*)(Om + orow1 + cc) = make_float2(oacc[nt][2] * invl1, oacc[nt][3] * invl1);
    }
}

// -------- TF32 tensor-core GEMM (dense layers) --------
// C = act(A @ B + bias) + res ; BM=128, BN=128, BK=16, 256 threads.
// If B2/B3 given (QKV fusion), blockIdx.z selects {B,C} among 3 pairs.
__global__ __launch_bounds__(256)
void gemm_tc(const float* __restrict__ A, int lda,
             const float* __restrict__ B0, const float* __restrict__ B1,
             const float* __restrict__ B2, int ldb,
             float* __restrict__ C0, float* __restrict__ C1,
             float* __restrict__ C2, int ldc,
             const float* __restrict__ res, const float* __restrict__ bias,
             int K, int act)
{
    constexpr int BN = 128;
    constexpr int ASTR = 20;
    constexpr int BSTR = BN + 8;
    constexpr int NT = BN / 16;

    __shared__ uint32_t As[2][128 * ASTR];
    __shared__ uint32_t Bs[2][16 * BSTR];

    const float* B = (blockIdx.z == 0) ? B0 : (blockIdx.z == 1 ? B1 : B2);
    float*       C = (blockIdx.z == 0) ? C0 : (blockIdx.z == 1 ? C1 : C2);

    const int tid  = threadIdx.x;
    const int lane = tid & 31, warp = tid >> 5;
    const int wm = warp & 3, wn = warp >> 2;
    const int gid = lane >> 2, tig = lane & 3;
    const int bm = blockIdx.y << 7;
    const int bn = blockIdx.x * BN;

    const int arow = tid >> 1, akc = (tid & 1) << 3;
    const float* Aptr = A + (long)(bm + arow) * lda + akc;
    const int bnrow = tid >> 4;
    const int bncol = (tid & 15) << 2;
    const float* Bptr = B + (long)bnrow * ldb + bn + bncol;

    float acc[2][NT][4];
    #pragma unroll
    for (int mt = 0; mt < 2; mt++)
        #pragma unroll
        for (int nt = 0; nt < NT; nt++)
            #pragma unroll
            for (int j = 0; j < 4; j++) acc[mt][nt][j] = 0.f;

    {
        float4 a0 = *(const float4*)Aptr, a1 = *(const float4*)(Aptr + 4);
        uint4 u0 = { f2t(a0.x), f2t(a0.y), f2t(a0.z), f2t(a0.w) };
        uint4 u1 = { f2t(a1.x), f2t(a1.y), f2t(a1.z), f2t(a1.w) };
        *(uint4*)&As[0][arow * ASTR + akc]     = u0;
        *(uint4*)&As[0][arow * ASTR + akc + 4] = u1;
        float4 b0 = *(const float4*)Bptr;
        float4 b1 = *(const float4*)(Bptr + 64);
        uint4 w0 = { f2t(b0.x), f2t(b0.y), f2t(b0.z), f2t(b0.w) };
        uint4 w1 = { f2t(b1.x), f2t(b1.y), f2t(b1.z), f2t(b1.w) };
        *(uint4*)&Bs[0][bnrow * BSTR + bncol]      = w0;
        *(uint4*)&Bs[0][bnrow * BSTR + bncol + 64] = w1;
    }
    __syncthreads();

    int buf = 0;
    const int nIter = K >> 4;
    for (int it = 0; it < nIter; ++it) {
        float4 na0, na1, nb0, nb1;
        const bool nx = (it + 1 < nIter);
        if (nx) {
            Aptr += 16;
            na0 = *(const float4*)Aptr; na1 = *(const float4*)(Aptr + 4);
            Bptr += (long)16 * ldb;
            nb0 = *(const float4*)Bptr; nb1 = *(const float4*)(Bptr + 64);
        }

        const uint32_t* as = As[buf];
        const uint32_t* bs = Bs[buf];
        #pragma unroll
        for (int kk = 0; kk < 2; kk++) {
            const int k0 = kk * 8;
            uint32_t af[2][4];
            #pragma unroll
            for (int mt = 0; mt < 2; mt++) {
                const int r = wm * 32 + mt * 16 + gid;
                af[mt][0] = as[r * ASTR + k0 + tig];
                af[mt][1] = as[(r + 8) * ASTR + k0 + tig];
                af[mt][2] = as[r * ASTR + k0 + tig + 4];
                af[mt][3] = as[(r + 8) * ASTR + k0 + tig + 4];
            }
            uint32_t bf[NT][2];
            #pragma unroll
            for (int nt = 0; nt < NT; nt++) {
                const int n = wn * (BN / 2) + nt * 8 + gid;
                bf[nt][0] = bs[(k0 + tig) * BSTR + n];
                bf[nt][1] = bs[(k0 + tig + 4) * BSTR + n];
            }
            #pragma unroll
            for (int mt = 0; mt < 2; mt++)
                #pragma unroll
                for (int nt = 0; nt < NT; nt++)
                    mma_tf32(acc[mt][nt], af[mt], bf[nt]);
        }

        if (nx) {
            const int nb = buf ^ 1;
            uint4 u0 = { f2t(na0.x), f2t(na0.y), f2t(na0.z), f2t(na0.w) };
            uint4 u1 = { f2t(na1.x), f2t(na1.y), f2t(na1.z), f2t(na1.w) };
            *(uint4*)&As[nb][arow * ASTR + akc]     = u0;
            *(uint4*)&As[nb][arow * ASTR + akc + 4] = u1;
            uint4 w0 = { f2t(nb0.x), f2t(nb0.y), f2t(nb0.z), f2t(nb0.w) };
            uint4 w1 = { f2t(nb1.x), f2t(nb1.y), f2t(nb1.z), f2t(nb1.w) };
            *(uint4*)&Bs[nb][bnrow * BSTR + bncol]      = w0;
            *(uint4*)&Bs[nb][bnrow * BSTR + bncol + 64] = w1;
            __syncthreads();
            buf ^= 1;
        }
    }

    #pragma unroll
    for (int mt = 0; mt < 2; mt++) {
        #pragma unroll
        for (int nt = 0; nt < NT; nt++) {
            const long r0 = bm + wm * 32 + mt * 16 + gid;
            const int  cc = bn + wn * (BN / 2) + nt * 8 + tig * 2;
            float2 bb = make_float2(0.f, 0.f);
            if (bias) bb = *(const float2*)(bias + cc);
            #pragma unroll
            for (int half = 0; half < 2; half++) {
                const long r = r0 + half * 8;
                float vx = acc[mt][nt][half * 2 + 0] + bb.x;
                float vy = acc[mt][nt][half * 2 + 1] + bb.y;
                if (act) {
                    vx = vx / (1.f + __expf(-vx));
                    vy = vy / (1.f + __expf(-vy));
                }
                if (res) {
                    const float2 rr = *(const float2*)(res + r * ldc + cc);
                    vx += rr.x; vy += rr.y;
                }
                *(float2*)(C + r * ldc + cc) = make_float2(vx, vy);
            }
        }
    }
}

// ---------------- host ----------------
extern "C" void kernel_launch(void* const* d_in, const int* in_sizes, int n_in,
                              void* d_out, int out_size)
{
    const float* x   = (const float*)d_in[0];
    const float* wq  = (const float*)d_in[1];
    const float* wk  = (const float*)d_in[2];
    const float* wv  = (const float*)d_in[3];
    const float* wo  = (const float*)d_in[4];
    const float* bo  = (const float*)d_in[5];
    const float* g1  = (const float*)d_in[6];
    const float* b1  = (const float*)d_in[7];
    const float* g2  = (const float*)d_in[8];
    const float* b2  = (const float*)d_in[9];
    const float* w1  = (const float*)d_in[10];
    const float* bf1 = (const float*)d_in[11];
    const float* w2  = (const float*)d_in[12];
    const float* bf2 = (const float*)d_in[13];
    float* out = (float*)d_out;

    float *h, *q, *k, *v, *att, *x1, *h2, *f1;
    cudaGetSymbolAddress((void**)&h,   g_h);
    cudaGetSymbolAddress((void**)&q,   g_q);
    cudaGetSymbolAddress((void**)&k,   g_k);
    cudaGetSymbolAddress((void**)&v,   g_v);
    cudaGetSymbolAddress((void**)&att, g_att);
    cudaGetSymbolAddress((void**)&x1,  g_x1);
    cudaGetSymbolAddress((void**)&h2,  g_h2);
    cudaGetSymbolAddress((void**)&f1,  g_f1);

    static bool attr_done = false;
    if (!attr_done) {
        cudaFuncSetAttribute(flash_attn, cudaFuncAttributeMaxDynamicSharedMemorySize,
                             FLASH_SMEM);
        attr_done = true;
    }

    // 1) LN1
    layernorm_kernel<<<MTOK, 128>>>(x, g1, b1, h);

    // 2) QKV fused: one launch, z selects weight/output
    dim3 gQKV(EDIM / 128, MTOK / 128, 3);
    gemm_tc<<<gQKV, 256>>>(h, 512, wq, wk, wv, 512, q, k, v, 512,
                           nullptr, nullptr, 512, 0);

    // 3-5) fused flash attention -> att
    flash_attn<<<dim3(16, 32), 256, FLASH_SMEM>>>(q, k, v, att);

    // 6) O projection + bias + residual(x)
    dim3 gProj(EDIM / 128, MTOK / 128, 1);
    gemm_tc<<<gProj, 256>>>(att, 512, wo, wo, wo, 512, x1, x1, x1, 512,
                            x, bo, 512, 0);

    // 7) LN2
    layernorm_kernel<<<MTOK, 128>>>(x1, g2, b2, h2);

    // 8) FFN1 + bias + SiLU
    dim3 gF1(FFDIM / 128, MTOK / 128, 1);
    gemm_tc<<<gF1, 256>>>(h2, 512, w1, w1, w1, FFDIM, f1, f1, f1, FFDIM,
                          nullptr, bf1, 512, 1);

    // 9) FFN2 + bias + residual(x1) -> out
    gemm_tc<<<gProj, 256>>>(f1, FFDIM, w2, w2, w2, 512, out, out, out, 512,
                            x1, bf2, FFDIM, 0);
}